// round 15
// baseline (speedup 1.0000x reference)
#include <cuda_runtime.h>
#include <cuda_bf16.h>
#include <cuda_fp16.h>
#include <math.h>

// Problem constants
#define BB 8
#define LL 2048
#define DD 1330
#define H1C 32
// T = 2 (hardcoded throughout)

#define NEGINF (-1e30f)
#define NTILE 42          // 2 K-slices * 21 tiles of 32 k

// Scratch (device globals; zero-initialized; no allocation allowed)
__device__ float g_p0[BB * LL * H1C];   // split-K partial 0
__device__ float g_p1[BB * LL * H1C];   // split-K partial 1
__device__ float g_em[BB * LL * 2];     // [B*L, 2]
__device__ float g_llh[BB];
__device__ unsigned g_done;
__device__ unsigned g_cnt[BB];          // conv blocks completed per batch (16)
__device__ unsigned g_prep;             // prep blocks completed (42)
__device__ unsigned g_stripe[128];      // gemm kslices done per 128-row stripe (2)
// B fragments, fragment-order: [tile][ch][ng][lane] -> {bh0,bh1,bm0,bm1}
__device__ uint4 g_bfrag[NTILE * 2 * 4 * 32];

// ---------------------------------------------------------------------------
// fp16 helpers
// ---------------------------------------------------------------------------
__device__ __forceinline__ void split_pair(float f0, float f1,
                                           unsigned& hi, unsigned& mid) {
    __half h0 = __float2half_rn(f0), h1 = __float2half_rn(f1);
    float r0 = f0 - __half2float(h0);
    float r1 = f1 - __half2float(h1);
    __half2 H = __halves2half2(h0, h1);
    __half2 M = __halves2half2(__float2half_rn(r0), __float2half_rn(r1));
    hi = *(unsigned*)&H;
    mid = *(unsigned*)&M;
}

#define MMA_F16(c, a0, a1, a2, a3, b0, b1)                                    \
    asm volatile(                                                             \
        "mma.sync.aligned.m16n8k16.row.col.f32.f16.f16.f32 "                  \
        "{%0,%1,%2,%3}, {%4,%5,%6,%7}, {%8,%9}, {%0,%1,%2,%3};"               \
        : "+f"(c[0]), "+f"(c[1]), "+f"(c[2]), "+f"(c[3])                      \
        : "r"(a0), "r"(a1), "r"(a2), "r"(a3), "r"(b0), "r"(b1))

__device__ __forceinline__ float2 ld2g(const float* __restrict__ r, int k) {
    return (k < DD) ? *(const float2*)(r + k) : make_float2(0.f, 0.f);
}

// ---------------------------------------------------------------------------
// CRF math helpers
// ---------------------------------------------------------------------------
__device__ __forceinline__ float4 max_mm(float4 A, float4 B) {
    float4 C;
    C.x = fmaxf(A.x + B.x, A.y + B.z);
    C.y = fmaxf(A.x + B.y, A.y + B.w);
    C.z = fmaxf(A.z + B.x, A.w + B.z);
    C.w = fmaxf(A.z + B.y, A.w + B.w);
    return C;
}
__device__ __forceinline__ unsigned comp2(unsigned a, unsigned b) {
    unsigned r0 = (a >> (b & 1)) & 1;
    unsigned r1 = (a >> ((b >> 1) & 1)) & 1;
    return r0 | (r1 << 1);
}
__device__ __forceinline__ float4 shfl_up4(float4 v, int off, unsigned m) {
    float4 r;
    r.x = __shfl_up_sync(m, v.x, off);
    r.y = __shfl_up_sync(m, v.y, off);
    r.z = __shfl_up_sync(m, v.z, off);
    r.w = __shfl_up_sync(m, v.w, off);
    return r;
}
__device__ __forceinline__ float4 shfl_dn4(float4 v, int off, unsigned m) {
    float4 r;
    r.x = __shfl_down_sync(m, v.x, off);
    r.y = __shfl_down_sync(m, v.y, off);
    r.z = __shfl_down_sync(m, v.z, off);
    r.w = __shfl_down_sync(m, v.w, off);
    return r;
}
// Linear-space (scaled-probability) ordered combine: (A,Sa) <- (A,Sa)*(B,Sb).
// Renormalizes by the max element; only 2 MUFU (rcp + log) per combine.
__device__ __forceinline__ void lin_comb(float4& A, float& Sa,
                                         float4 B, float Sb) {
    float x = A.x * B.x + A.y * B.z;
    float y = A.x * B.y + A.y * B.w;
    float z = A.z * B.x + A.w * B.z;
    float w = A.z * B.y + A.w * B.w;
    float m = fmaxf(fmaxf(x, y), fmaxf(z, w));
    float inv = __frcp_rn(m);
    A = make_float4(x * inv, y * inv, z * inv, w * inv);
    Sa = Sa + Sb + __logf(m);
}

// ---------------------------------------------------------------------------
// MEGA-KERNEL: prep + gemm + conv + crf in one launch.
// Grid 256 x 256 threads, launch_bounds(256,2) -> all blocks co-resident.
//   Phase P: blocks 0..41 build B fragments, signal g_prep.
//   Phase G: all blocks gemm; block = (stripe=bid>>1, kslice=bid&1);
//            epilogue signals g_stripe[stripe].
//   Phase C: blocks 0..127 conv (128 pos each, 2 thr/pos); wait on the
//            <=3 stripes they read; signal g_cnt[batch].
//   Phase R: blocks 128..135 CRF per batch (linear-space forward);
//            last one reduces loss + resets all counters.
//   Blocks 136..255 exit after Phase G.
// ---------------------------------------------------------------------------
__global__ __launch_bounds__(256, 2) void fused_all(
    const float* __restrict__ x, const float* __restrict__ w1,
    const float* __restrict__ b1,
    const float* __restrict__ conv_w, const float* __restrict__ conv_b,
    const float* __restrict__ w2, const float* __restrict__ b2,
    const int* __restrict__ tlen, const int* __restrict__ labels,
    const float* __restrict__ start_trans, const float* __restrict__ end_trans,
    const float* __restrict__ trans, float* __restrict__ out)
{
    __shared__ __align__(16) float wst[96][16];
    __shared__ __align__(16) float hs[130][33];
    __shared__ float cb[16];
    __shared__ float w2s[16][2];
    __shared__ float b2s[2];
    __shared__ float b1s[32];
    __shared__ float4 wf8[8];      // per-warp forward linear products
    __shared__ float  wfS[8];      // ... and their log offsets
    __shared__ float4 wv8[8];
    __shared__ float4 wvscan[8];
    __shared__ float4 pftot_s;
    __shared__ float  pftot_S;
    __shared__ unsigned wc[8];
    __shared__ float ss[8];

    const int tid = threadIdx.x;
    const int bid = blockIdx.x;
    const int warp = tid >> 5, lane = tid & 31;
    const int gr = lane >> 2, gc = lane & 3;
    const unsigned FULL = 0xffffffffu;

    // =================== PHASE G setup + tile-0 prefetch ===================
    const int stripe = bid >> 1;
    const int ksl = bid & 1;
    const int row0 = stripe * 128;
    const int kbase = ksl * 672;

    const float* __restrict__ rowA = x + (size_t)(row0 + warp * 16 + gr) * DD;
    const float* __restrict__ rowB = rowA + 8 * (size_t)DD;

    float2 cur[8], nxt[8];
    {
        int kq0 = kbase + 8 * gc;
#pragma unroll
        for (int ch = 0; ch < 2; ch++) {
            int kq = kq0 + 4 * ch;
            cur[ch * 4 + 0] = ld2g(rowA, kq);
            cur[ch * 4 + 1] = ld2g(rowA, kq + 2);
            cur[ch * 4 + 2] = ld2g(rowB, kq);
            cur[ch * 4 + 3] = ld2g(rowB, kq + 2);
        }
    }

    // =================== PHASE P: B-prep (blocks 0..41) ===================
    if (bid < 42) {
        int idx = bid * 256 + tid;          // 0..10751
        int elane = idx & 31;
        int eng = (idx >> 5) & 3;
        int ech = (idx >> 7) & 1;
        int et = idx >> 8;                   // 0..41
        int egr = elane >> 2, egc = elane & 3;
        int c = eng * 8 + egr;
        int kb = et * 32 + 8 * egc + 4 * ech;
        float f[4];
#pragma unroll
        for (int b2i = 0; b2i < 4; b2i++) {
            int k = kb + b2i;
            f[b2i] = (k < DD) ? w1[k * H1C + c] : 0.f;
        }
        uint4 o;
        split_pair(f[0], f[1], o.x, o.z);
        split_pair(f[2], f[3], o.y, o.w);
        g_bfrag[idx] = o;
        __threadfence();
        __syncthreads();
        if (tid == 0) atomicAdd(&g_prep, 1u);
    }

    if (tid == 0) {
        while (*(volatile unsigned*)&g_prep < 42u) { }
    }
    __syncthreads();
    __threadfence();

    // =================== PHASE G: gemm main loop ===================
    float acc[4][4];
#pragma unroll
    for (int n = 0; n < 4; n++)
#pragma unroll
        for (int r = 0; r < 4; r++) acc[n][r] = 0.f;

#pragma unroll
    for (int t = 0; t < 21; t++) {
        if (t < 20) {
            int kq0 = kbase + (t + 1) * 32 + 8 * gc;
#pragma unroll
            for (int ch = 0; ch < 2; ch++) {
                int kq = kq0 + 4 * ch;
                nxt[ch * 4 + 0] = ld2g(rowA, kq);
                nxt[ch * 4 + 1] = ld2g(rowA, kq + 2);
                nxt[ch * 4 + 2] = ld2g(rowB, kq);
                nxt[ch * 4 + 3] = ld2g(rowB, kq + 2);
            }
        }

        const uint4* __restrict__ bf =
            g_bfrag + (size_t)(ksl * 21 + t) * 256 + lane;

#pragma unroll
        for (int ch = 0; ch < 2; ch++) {
            uint4 B0 = bf[ch * 128 + 0];
            uint4 B1 = bf[ch * 128 + 32];
            uint4 B2 = bf[ch * 128 + 64];
            uint4 B3 = bf[ch * 128 + 96];

            float2 p0 = cur[ch * 4 + 0], p1 = cur[ch * 4 + 1];
            float2 q0 = cur[ch * 4 + 2], q1 = cur[ch * 4 + 3];
            unsigned ah0, ah1, ah2, ah3, am0, am1, am2, am3;
            split_pair(p0.x, p0.y, ah0, am0);
            split_pair(q0.x, q0.y, ah1, am1);
            split_pair(p1.x, p1.y, ah2, am2);
            split_pair(q1.x, q1.y, ah3, am3);

            MMA_F16(acc[0], ah0, ah1, ah2, ah3, B0.x, B0.y);
            MMA_F16(acc[0], ah0, ah1, ah2, ah3, B0.z, B0.w);
            MMA_F16(acc[0], am0, am1, am2, am3, B0.x, B0.y);

            MMA_F16(acc[1], ah0, ah1, ah2, ah3, B1.x, B1.y);
            MMA_F16(acc[1], ah0, ah1, ah2, ah3, B1.z, B1.w);
            MMA_F16(acc[1], am0, am1, am2, am3, B1.x, B1.y);

            MMA_F16(acc[2], ah0, ah1, ah2, ah3, B2.x, B2.y);
            MMA_F16(acc[2], ah0, ah1, ah2, ah3, B2.z, B2.w);
            MMA_F16(acc[2], am0, am1, am2, am3, B2.x, B2.y);

            MMA_F16(acc[3], ah0, ah1, ah2, ah3, B3.x, B3.y);
            MMA_F16(acc[3], ah0, ah1, ah2, ah3, B3.z, B3.w);
            MMA_F16(acc[3], am0, am1, am2, am3, B3.x, B3.y);
        }

#pragma unroll
        for (int i = 0; i < 8; i++) cur[i] = nxt[i];
    }

    {
        float* gp = ksl ? g_p1 : g_p0;
        const int rowa = row0 + warp * 16 + gr;
#pragma unroll
        for (int ng = 0; ng < 4; ng++) {
            int col = ng * 8 + 2 * gc;
            *(float2*)&gp[(size_t)rowa * H1C + col] =
                make_float2(acc[ng][0], acc[ng][1]);
            *(float2*)&gp[(size_t)(rowa + 8) * H1C + col] =
                make_float2(acc[ng][2], acc[ng][3]);
        }
    }
    __threadfence();
    __syncthreads();
    if (tid == 0) atomicAdd(&g_stripe[stripe], 1u);

    if (bid >= 136) return;

    if (bid < 128) {
        // ============ PHASE C: conv (blocks 0..127, 128 pos each) ============
        for (int i = tid; i < 96 * 16; i += 256) {
            int q = i >> 4, c2 = i & 15;
            int k = q >> 5, c1 = q & 31;
            wst[q][c2] = conv_w[c2 * 96 + c1 * 3 + k];
        }
        if (tid < 16) cb[tid] = conv_b[tid];
        if (tid < 32) { w2s[tid >> 1][tid & 1] = w2[tid]; b1s[tid] = b1[tid]; }
        if (tid < 2) b2s[tid] = b2[tid];

        const int p0 = bid * 128;
        const int lblk = p0 & (LL - 1);

        // stripes read: rows p0-1 .. p0+128 -> stripes bid-1..bid+1 (clamped)
        const int s_lo = (lblk > 0) ? (bid - 1) : bid;
        const int s_hi = (lblk + 128 < LL) ? (bid + 1) : bid;

        if (tid == 0) {
            for (int s = s_lo; s <= s_hi; s++) {
                while (*(volatile unsigned*)&g_stripe[s] < 2u) { }
            }
        }
        __syncthreads();
        __threadfence();

        for (int idx = tid; idx < 130 * 32; idx += 256) {
            int row = idx >> 5, c = idx & 31;
            int l = lblk - 1 + row;
            float v = 0.f;
            if (l >= 0 && l < LL) {
                int g = p0 + row - 1;
                v = g_p0[(size_t)g * H1C + c] + g_p1[(size_t)g * H1C + c] + b1s[c];
            }
            hs[row][c] = v;
        }
        __syncthreads();

        const int i = tid >> 1;     // position 0..127
        const int h = tid & 1;      // half of the 96-term reduction

        float4 cacc[4];
#pragma unroll
        for (int m = 0; m < 4; m++) cacc[m] = make_float4(0, 0, 0, 0);
#pragma unroll
        for (int j = 0; j < 48; j++) {
            int q = h * 48 + j;
            int kk = q >> 5, c1 = q & 31;
            float hv = hs[i + kk][c1];
#pragma unroll
            for (int m = 0; m < 4; m++) {
                float4 w = *(const float4*)&wst[q][m * 4];
                cacc[m].x += hv * w.x; cacc[m].y += hv * w.y;
                cacc[m].z += hv * w.z; cacc[m].w += hv * w.w;
            }
        }
        float af[16];
#pragma unroll
        for (int m = 0; m < 4; m++) {
            af[m * 4 + 0] = cacc[m].x; af[m * 4 + 1] = cacc[m].y;
            af[m * 4 + 2] = cacc[m].z; af[m * 4 + 3] = cacc[m].w;
        }
#pragma unroll
        for (int m = 0; m < 16; m++)
            af[m] += __shfl_xor_sync(FULL, af[m], 1);

        if (h == 0) {
            float e0 = b2s[0], e1 = b2s[1];
#pragma unroll
            for (int c2 = 0; c2 < 16; c2++) {
                float hh = fmaxf(af[c2] + cb[c2], 0.f);
                e0 += hh * w2s[c2][0];
                e1 += hh * w2s[c2][1];
            }
            *(float2*)&g_em[(size_t)(p0 + i) * 2] = make_float2(e0, e1);
        }

        __threadfence();
        __syncthreads();
        if (tid == 0) atomicAdd(&g_cnt[p0 >> 11], 1u);
        return;
    }

    // =================== PHASE R: CRF (blocks 128..135) ===================
    const int b = bid - 128;
    const int wid = warp;
    const int len = tlen[b];
    const float t00 = trans[0], t01 = trans[1], t10 = trans[2], t11 = trans[3];
    const float* emb = g_em + (size_t)b * LL * 2;
    const float4 IDENT = make_float4(0.f, NEGINF, NEGINF, 0.f);

    // prefetch labels (independent of conv)
    const int* lab = labels + (size_t)b * LL;
    int labv[9];
#pragma unroll
    for (int k = 0; k < 9; k++) {
        int t = tid * 8 + k;
        labv[k] = (t < LL) ? lab[t] : 0;
    }
    // precompute exp of transitions (tiny)
    const float et00 = __expf(t00), et01 = __expf(t01);
    const float et10 = __expf(t10), et11 = __expf(t11);

    if (tid == 0) {
        while (*(volatile unsigned*)&g_cnt[b] < 16u) { }
    }
    __syncthreads();
    __threadfence();

    float2 em[8];
#pragma unroll
    for (int k = 0; k < 8; k++) {
        int t = tid * 8 + k + 1;
        em[k] = (t < LL) ? *(const float2*)(emb + 2 * t) : make_float2(0.f, 0.f);
    }

    // ---- forward chunk product in LINEAR space (scaled) ----
    float4 Lf = make_float4(1.f, 0.f, 0.f, 1.f);
    float Sf = 0.f;
    // ---- viterbi chunk product (max-plus, log space) ----
    float4 Pv;
    if (tid * 8 + 1 >= len) {
        Pv = IDENT;
    } else {
#pragma unroll
        for (int k = 0; k < 8; k++) {
            int t = tid * 8 + k + 1;
            if (t < len) {
                float m0 = em[k].x, m1 = em[k].y;
                float c = fmaxf(m0, m1);
                float p0 = __expf(m0 - c), p1 = __expf(m1 - c);
                float r0 = et00 * p0, r1 = et01 * p1;
                float r2 = et10 * p0, r3 = et11 * p1;
                float nx = Lf.x * r0 + Lf.y * r2;
                float ny = Lf.x * r1 + Lf.y * r3;
                float nz = Lf.z * r0 + Lf.w * r2;
                float nw = Lf.z * r1 + Lf.w * r3;
                Lf = make_float4(nx, ny, nz, nw);
                Sf += c;
            }
        }
        float4 M[8];
#pragma unroll
        for (int k = 0; k < 8; k++) {
            int t = tid * 8 + k + 1;
            M[k] = (t < len)
                ? make_float4(t00 + em[k].x, t01 + em[k].y, t10 + em[k].x, t11 + em[k].y)
                : IDENT;
        }
        float4 v01 = max_mm(M[0], M[1]), v23 = max_mm(M[2], M[3]);
        float4 v45 = max_mm(M[4], M[5]), v67 = max_mm(M[6], M[7]);
        Pv = max_mm(max_mm(v01, v23), max_mm(v45, v67));
    }

    // ---- forward: warp reduce in linear space (ordered, gated) ----
    {
        float4 r = Lf; float rs = Sf;
#pragma unroll
        for (int off = 1; off < 32; off <<= 1) {
            float4 o = shfl_dn4(r, off, FULL);
            float os = __shfl_down_sync(FULL, rs, off);
            if (lane + off < 32) lin_comb(r, rs, o, os);
        }
        if (lane == 0) { wf8[wid] = r; wfS[wid] = rs; }
    }

    // ---- viterbi: warp inclusive scan ----
    float4 s = Pv;
#pragma unroll
    for (int off = 1; off < 32; off <<= 1) {
        float4 o = shfl_up4(s, off, FULL);
        if (lane >= off) s = max_mm(o, s);
    }
    if (lane == 31) wv8[wid] = s;
    __syncthreads();

    if (wid == 0 && lane < 8) {
        float4 rf = wf8[lane]; float rfs = wfS[lane];
#pragma unroll
        for (int off = 1; off < 8; off <<= 1) {
            float4 o = shfl_dn4(rf, off, 0xffu);
            float os = __shfl_down_sync(0xffu, rfs, off);
            if (lane + off < 8) lin_comb(rf, rfs, o, os);
        }
        if (lane == 0) { pftot_s = rf; pftot_S = rfs; }

        float4 rv = wv8[lane];
#pragma unroll
        for (int off = 1; off < 8; off <<= 1) {
            float4 o = shfl_up4(rv, off, 0xffu);
            if (lane >= off) rv = max_mm(o, rv);
        }
        wvscan[lane] = rv;
    }
    __syncthreads();

    const float a00 = start_trans[0] + emb[0];
    const float a01 = start_trans[1] + emb[1];
    const float e0 = end_trans[0], e1 = end_trans[1];

    float4 PVt = wvscan[7];
    float v0 = fmaxf(a00 + PVt.x, a01 + PVt.z);
    float v1 = fmaxf(a00 + PVt.y, a01 + PVt.w);
    const int last = (v1 + e1 > v0 + e0) ? 1 : 0;

    float4 prev = shfl_up4(s, 1, FULL);
    float4 E;
    if (wid == 0) E = (lane == 0) ? IDENT : prev;
    else          E = (lane == 0) ? wvscan[wid - 1] : max_mm(wvscan[wid - 1], prev);

    float u0 = fmaxf(a00 + E.x, a01 + E.z);
    float u1 = fmaxf(a00 + E.y, a01 + E.w);
    unsigned g[8];
    unsigned cc = 2u;
#pragma unroll
    for (int k = 0; k < 8; k++) {
        int t = tid * 8 + k + 1;
        unsigned gt;
        if (t < len) {
            float m0 = em[k].x, m1 = em[k].y;
            float s00 = u0 + t00, s10 = u1 + t10;
            int i0 = (s10 > s00) ? 1 : 0;
            float n0 = fmaxf(s00, s10) + m0;
            float s01 = u0 + t01, s11 = u1 + t11;
            int i1 = (s11 > s01) ? 1 : 0;
            float n1 = fmaxf(s01, s11) + m1;
            gt = (unsigned)(i0 | (i1 << 1));
            u0 = n0; u1 = n1;
        } else {
            gt = 2u;
        }
        g[k] = gt;
        cc = comp2(cc, gt);
    }

    unsigned vsuf = cc;
#pragma unroll
    for (int off = 1; off < 32; off <<= 1) {
        unsigned o = __shfl_down_sync(FULL, vsuf, off);
        if (lane + off < 32) vsuf = comp2(vsuf, o);
    }
    if (lane == 0) wc[wid] = vsuf;
    __syncthreads();

    unsigned nv = __shfl_down_sync(FULL, vsuf, 1);
    unsigned within = (lane == 31) ? 2u : nv;
    unsigned ws = 2u;
#pragma unroll
    for (int j = 0; j < 8; j++)
        if (j > wid) ws = comp2(ws, wc[j]);
    unsigned suf_next = comp2(within, ws);
    unsigned xx = (suf_next >> last) & 1u;

    float* tout = out + 1 + (size_t)b * LL;
#pragma unroll
    for (int k = 7; k >= 0; k--) {
        xx = (g[k] >> xx) & 1u;
        int pos = tid * 8 + k;
        tout[pos] = (pos < len) ? (float)xx : 0.f;
    }

    float sc = 0.f;
#pragma unroll
    for (int k = 0; k < 8; k++) {
        int t = tid * 8 + k + 1;
        if (t < len) {
            int lp = labv[k], lc = labv[k + 1];
            sc += trans[lp * 2 + lc] + (lc ? em[k].y : em[k].x);
        }
    }
#pragma unroll
    for (int off = 1; off < 32; off <<= 1) {
        float o = __shfl_down_sync(FULL, sc, off);
        if (lane + off < 32) sc += o;
    }
    if (lane == 0) ss[wid] = sc;
    __syncthreads();

    if (tid == 0) {
        // norm from linear product + scale
        float4 PF = pftot_s;
        float PS = pftot_S;
        float ca = fmaxf(a00, a01);
        float va = __expf(a00 - ca), vb = __expf(a01 - ca);
        float r0 = va * PF.x + vb * PF.z;
        float r1 = va * PF.y + vb * PF.w;
        float q = r0 * __expf(e0) + r1 * __expf(e1);
        float norm = __logf(q) + PS + ca;

        float total = 0.f;
#pragma unroll
        for (int i = 0; i < 8; i++) total += ss[i];
        int l0 = lab[0];
        total += start_trans[l0] + emb[l0];
        int le = lab[len - 1];
        total += end_trans[le];
        g_llh[b] = total - norm;
        __threadfence();
        unsigned old = atomicAdd(&g_done, 1);
        if (old == BB - 1) {
            __threadfence();
            float sacc = 0.f;
#pragma unroll
            for (int i = 0; i < BB; i++) sacc += ((volatile float*)g_llh)[i];
            out[0] = -sacc;
            // reset all sync state for the next graph replay
            g_done = 0;
            g_prep = 0;
#pragma unroll
            for (int i = 0; i < BB; i++) g_cnt[i] = 0;
            for (int i = 0; i < 128; i++) g_stripe[i] = 0;
            __threadfence();
        }
    }
}

extern "C" void kernel_launch(void* const* d_in, const int* in_sizes, int n_in,
                              void* d_out, int out_size)
{
    const float* x       = (const float*)d_in[0];
    const int*   tlen    = (const int*)d_in[1];
    const int*   labels  = (const int*)d_in[2];
    const float* w1      = (const float*)d_in[3];
    const float* b1      = (const float*)d_in[4];
    const float* conv_w  = (const float*)d_in[5];
    const float* conv_b  = (const float*)d_in[6];
    const float* w2      = (const float*)d_in[7];
    const float* b2      = (const float*)d_in[8];
    const float* st      = (const float*)d_in[9];
    const float* en      = (const float*)d_in[10];
    const float* tr      = (const float*)d_in[11];
    float* out = (float*)d_out;

    fused_all<<<256, 256>>>(x, w1, b1, conv_w, conv_b, w2, b2,
                            tlen, labels, st, en, tr, out);
}

// round 16
// speedup vs baseline: 1.0447x; 1.0447x over previous
#include <cuda_runtime.h>
#include <cuda_bf16.h>
#include <cuda_fp16.h>
#include <math.h>

// Problem constants
#define BB 8
#define LL 2048
#define DD 1330
#define H1C 32
// T = 2 (hardcoded throughout)

#define NEGINF (-1e30f)
#define NTILE 42          // 2 K-slices * 21 tiles of 32 k

// Scratch (device globals; zero-initialized; no allocation allowed)
__device__ float g_p0[BB * LL * H1C];   // split-K partial 0
__device__ float g_p1[BB * LL * H1C];   // split-K partial 1
__device__ float g_em[BB * LL * 2];     // [B*L, 2]
__device__ float g_llh[BB];
__device__ unsigned g_done;
__device__ unsigned g_cnt[BB];          // conv blocks completed per batch (8)
__device__ unsigned g_prep;             // prep blocks completed (42)
__device__ unsigned g_stripe[128];      // gemm kslices done per 128-row stripe (2)
// B fragments, fragment-order: [tile][ch][ng][lane] -> {bh0,bh1,bm0,bm1}
__device__ uint4 g_bfrag[NTILE * 2 * 4 * 32];

// ---------------------------------------------------------------------------
// fp16 helpers
// ---------------------------------------------------------------------------
__device__ __forceinline__ void split_pair(float f0, float f1,
                                           unsigned& hi, unsigned& mid) {
    __half h0 = __float2half_rn(f0), h1 = __float2half_rn(f1);
    float r0 = f0 - __half2float(h0);
    float r1 = f1 - __half2float(h1);
    __half2 H = __halves2half2(h0, h1);
    __half2 M = __halves2half2(__float2half_rn(r0), __float2half_rn(r1));
    hi = *(unsigned*)&H;
    mid = *(unsigned*)&M;
}

#define MMA_F16(c, a0, a1, a2, a3, b0, b1)                                    \
    asm volatile(                                                             \
        "mma.sync.aligned.m16n8k16.row.col.f32.f16.f16.f32 "                  \
        "{%0,%1,%2,%3}, {%4,%5,%6,%7}, {%8,%9}, {%0,%1,%2,%3};"               \
        : "+f"(c[0]), "+f"(c[1]), "+f"(c[2]), "+f"(c[3])                      \
        : "r"(a0), "r"(a1), "r"(a2), "r"(a3), "r"(b0), "r"(b1))

__device__ __forceinline__ float2 ld2g(const float* __restrict__ r, int k) {
    return (k < DD) ? *(const float2*)(r + k) : make_float2(0.f, 0.f);
}

// ---------------------------------------------------------------------------
// CRF math helpers
// ---------------------------------------------------------------------------
__device__ __forceinline__ float4 max_mm(float4 A, float4 B) {
    float4 C;
    C.x = fmaxf(A.x + B.x, A.y + B.z);
    C.y = fmaxf(A.x + B.y, A.y + B.w);
    C.z = fmaxf(A.z + B.x, A.w + B.z);
    C.w = fmaxf(A.z + B.y, A.w + B.w);
    return C;
}
__device__ __forceinline__ unsigned comp2(unsigned a, unsigned b) {
    unsigned r0 = (a >> (b & 1)) & 1;
    unsigned r1 = (a >> ((b >> 1) & 1)) & 1;
    return r0 | (r1 << 1);
}
__device__ __forceinline__ float4 shfl_up4(float4 v, int off, unsigned m) {
    float4 r;
    r.x = __shfl_up_sync(m, v.x, off);
    r.y = __shfl_up_sync(m, v.y, off);
    r.z = __shfl_up_sync(m, v.z, off);
    r.w = __shfl_up_sync(m, v.w, off);
    return r;
}
__device__ __forceinline__ float4 shfl_dn4(float4 v, int off, unsigned m) {
    float4 r;
    r.x = __shfl_down_sync(m, v.x, off);
    r.y = __shfl_down_sync(m, v.y, off);
    r.z = __shfl_down_sync(m, v.z, off);
    r.w = __shfl_down_sync(m, v.w, off);
    return r;
}
// Linear-space (scaled-probability) ordered combine: (A,Sa) <- (A,Sa)*(B,Sb).
// Renormalizes by the max element; only 2 MUFU (rcp + log) per combine.
__device__ __forceinline__ void lin_comb(float4& A, float& Sa,
                                         float4 B, float Sb) {
    float x = A.x * B.x + A.y * B.z;
    float y = A.x * B.y + A.y * B.w;
    float z = A.z * B.x + A.w * B.z;
    float w = A.z * B.y + A.w * B.w;
    float m = fmaxf(fmaxf(x, y), fmaxf(z, w));
    float inv = __frcp_rn(m);
    A = make_float4(x * inv, y * inv, z * inv, w * inv);
    Sa = Sa + Sb + __logf(m);
}

// ---------------------------------------------------------------------------
// MEGA-KERNEL: prep + gemm + conv + crf in one launch.
// Grid 256 x 256 threads, launch_bounds(256,2) -> all blocks co-resident.
//   Phase P: blocks 0..41 build B fragments, signal g_prep.
//   Phase G: all blocks gemm; block = (stripe=bid>>1, kslice=bid&1);
//            epilogue signals g_stripe[stripe].
//   Phase C: blocks 0..63 conv (256 pos each); wait on the <=4 stripes they
//            read; signal g_cnt[batch].
//   Phase R: blocks 64..71 CRF per batch (LINEAR-SPACE forward = few MUFU);
//            last one reduces loss + resets all counters.
//   Blocks 72..255 exit after Phase G.
// ---------------------------------------------------------------------------
__global__ __launch_bounds__(256, 2) void fused_all(
    const float* __restrict__ x, const float* __restrict__ w1,
    const float* __restrict__ b1,
    const float* __restrict__ conv_w, const float* __restrict__ conv_b,
    const float* __restrict__ w2, const float* __restrict__ b2,
    const int* __restrict__ tlen, const int* __restrict__ labels,
    const float* __restrict__ start_trans, const float* __restrict__ end_trans,
    const float* __restrict__ trans, float* __restrict__ out)
{
    __shared__ __align__(16) float wst[96][16];
    __shared__ __align__(16) float hs[258][33];
    __shared__ float cb[16];
    __shared__ float w2s[16][2];
    __shared__ float b2s[2];
    __shared__ float b1s[32];
    __shared__ float4 wf8[8];      // per-warp forward linear products
    __shared__ float  wfS[8];      // ... and their log offsets
    __shared__ float4 wv8[8];
    __shared__ float4 wvscan[8];
    __shared__ float4 pftot_s;
    __shared__ float  pftot_S;
    __shared__ unsigned wc[8];
    __shared__ float ss[8];

    const int tid = threadIdx.x;
    const int bid = blockIdx.x;
    const int warp = tid >> 5, lane = tid & 31;
    const int gr = lane >> 2, gc = lane & 3;
    const unsigned FULL = 0xffffffffu;

    // =================== PHASE G setup + tile-0 prefetch ===================
    const int stripe = bid >> 1;
    const int ksl = bid & 1;
    const int row0 = stripe * 128;
    const int kbase = ksl * 672;

    const float* __restrict__ rowA = x + (size_t)(row0 + warp * 16 + gr) * DD;
    const float* __restrict__ rowB = rowA + 8 * (size_t)DD;

    float2 cur[8], nxt[8];
    {
        int kq0 = kbase + 8 * gc;
#pragma unroll
        for (int ch = 0; ch < 2; ch++) {
            int kq = kq0 + 4 * ch;
            cur[ch * 4 + 0] = ld2g(rowA, kq);
            cur[ch * 4 + 1] = ld2g(rowA, kq + 2);
            cur[ch * 4 + 2] = ld2g(rowB, kq);
            cur[ch * 4 + 3] = ld2g(rowB, kq + 2);
        }
    }

    // =================== PHASE P: B-prep (blocks 0..41) ===================
    if (bid < 42) {
        int idx = bid * 256 + tid;          // 0..10751
        int elane = idx & 31;
        int eng = (idx >> 5) & 3;
        int ech = (idx >> 7) & 1;
        int et = idx >> 8;                   // 0..41
        int egr = elane >> 2, egc = elane & 3;
        int c = eng * 8 + egr;
        int kb = et * 32 + 8 * egc + 4 * ech;
        float f[4];
#pragma unroll
        for (int b2i = 0; b2i < 4; b2i++) {
            int k = kb + b2i;
            f[b2i] = (k < DD) ? w1[k * H1C + c] : 0.f;
        }
        uint4 o;
        split_pair(f[0], f[1], o.x, o.z);
        split_pair(f[2], f[3], o.y, o.w);
        g_bfrag[idx] = o;
        __threadfence();
        __syncthreads();
        if (tid == 0) atomicAdd(&g_prep, 1u);
    }

    if (tid == 0) {
        while (*(volatile unsigned*)&g_prep < 42u) { }
    }
    __syncthreads();
    __threadfence();

    // =================== PHASE G: gemm main loop ===================
    float acc[4][4];
#pragma unroll
    for (int n = 0; n < 4; n++)
#pragma unroll
        for (int r = 0; r < 4; r++) acc[n][r] = 0.f;

#pragma unroll
    for (int t = 0; t < 21; t++) {
        if (t < 20) {
            int kq0 = kbase + (t + 1) * 32 + 8 * gc;
#pragma unroll
            for (int ch = 0; ch < 2; ch++) {
                int kq = kq0 + 4 * ch;
                nxt[ch * 4 + 0] = ld2g(rowA, kq);
                nxt[ch * 4 + 1] = ld2g(rowA, kq + 2);
                nxt[ch * 4 + 2] = ld2g(rowB, kq);
                nxt[ch * 4 + 3] = ld2g(rowB, kq + 2);
            }
        }

        const uint4* __restrict__ bf =
            g_bfrag + (size_t)(ksl * 21 + t) * 256 + lane;

#pragma unroll
        for (int ch = 0; ch < 2; ch++) {
            uint4 B0 = bf[ch * 128 + 0];
            uint4 B1 = bf[ch * 128 + 32];
            uint4 B2 = bf[ch * 128 + 64];
            uint4 B3 = bf[ch * 128 + 96];

            float2 p0 = cur[ch * 4 + 0], p1 = cur[ch * 4 + 1];
            float2 q0 = cur[ch * 4 + 2], q1 = cur[ch * 4 + 3];
            unsigned ah0, ah1, ah2, ah3, am0, am1, am2, am3;
            split_pair(p0.x, p0.y, ah0, am0);
            split_pair(q0.x, q0.y, ah1, am1);
            split_pair(p1.x, p1.y, ah2, am2);
            split_pair(q1.x, q1.y, ah3, am3);

            MMA_F16(acc[0], ah0, ah1, ah2, ah3, B0.x, B0.y);
            MMA_F16(acc[0], ah0, ah1, ah2, ah3, B0.z, B0.w);
            MMA_F16(acc[0], am0, am1, am2, am3, B0.x, B0.y);

            MMA_F16(acc[1], ah0, ah1, ah2, ah3, B1.x, B1.y);
            MMA_F16(acc[1], ah0, ah1, ah2, ah3, B1.z, B1.w);
            MMA_F16(acc[1], am0, am1, am2, am3, B1.x, B1.y);

            MMA_F16(acc[2], ah0, ah1, ah2, ah3, B2.x, B2.y);
            MMA_F16(acc[2], ah0, ah1, ah2, ah3, B2.z, B2.w);
            MMA_F16(acc[2], am0, am1, am2, am3, B2.x, B2.y);

            MMA_F16(acc[3], ah0, ah1, ah2, ah3, B3.x, B3.y);
            MMA_F16(acc[3], ah0, ah1, ah2, ah3, B3.z, B3.w);
            MMA_F16(acc[3], am0, am1, am2, am3, B3.x, B3.y);
        }

#pragma unroll
        for (int i = 0; i < 8; i++) cur[i] = nxt[i];
    }

    {
        float* gp = ksl ? g_p1 : g_p0;
        const int rowa = row0 + warp * 16 + gr;
#pragma unroll
        for (int ng = 0; ng < 4; ng++) {
            int col = ng * 8 + 2 * gc;
            *(float2*)&gp[(size_t)rowa * H1C + col] =
                make_float2(acc[ng][0], acc[ng][1]);
            *(float2*)&gp[(size_t)(rowa + 8) * H1C + col] =
                make_float2(acc[ng][2], acc[ng][3]);
        }
    }
    __threadfence();
    __syncthreads();
    if (tid == 0) atomicAdd(&g_stripe[stripe], 1u);

    if (bid >= 72) return;

    if (bid < 64) {
        // =================== PHASE C: conv (blocks 0..63) ===================
        for (int i = tid; i < 96 * 16; i += 256) {
            int q = i >> 4, c2 = i & 15;
            int k = q >> 5, c1 = q & 31;
            wst[q][c2] = conv_w[c2 * 96 + c1 * 3 + k];
        }
        if (tid < 16) cb[tid] = conv_b[tid];
        if (tid < 32) { w2s[tid >> 1][tid & 1] = w2[tid]; b1s[tid] = b1[tid]; }
        if (tid < 2) b2s[tid] = b2[tid];

        const int p0 = bid * 256;
        const int lblk = p0 & (LL - 1);

        // stripes read: rows p0-1 .. p0+256 (halo clamped to batch)
        const int s_lo = (lblk > 0) ? (2 * bid - 1) : (2 * bid);
        const int s_hi = (lblk + 256 < LL) ? (2 * bid + 2) : (2 * bid + 1);

        if (tid == 0) {
            for (int s = s_lo; s <= s_hi; s++) {
                while (*(volatile unsigned*)&g_stripe[s] < 2u) { }
            }
        }
        __syncthreads();
        __threadfence();

        for (int idx = tid; idx < 258 * 32; idx += 256) {
            int row = idx >> 5, c = idx & 31;
            int l = lblk - 1 + row;
            float v = 0.f;
            if (l >= 0 && l < LL) {
                int g = p0 + row - 1;
                v = g_p0[(size_t)g * H1C + c] + g_p1[(size_t)g * H1C + c] + b1s[c];
            }
            hs[row][c] = v;
        }
        __syncthreads();

        float4 cacc[4];
#pragma unroll
        for (int m = 0; m < 4; m++) cacc[m] = make_float4(0, 0, 0, 0);
#pragma unroll
        for (int kk = 0; kk < 3; kk++) {
#pragma unroll
            for (int c1 = 0; c1 < 32; c1++) {
                float hv = hs[tid + kk][c1];
                int q = kk * 32 + c1;
#pragma unroll
                for (int m = 0; m < 4; m++) {
                    float4 w = *(const float4*)&wst[q][m * 4];
                    cacc[m].x += hv * w.x; cacc[m].y += hv * w.y;
                    cacc[m].z += hv * w.z; cacc[m].w += hv * w.w;
                }
            }
        }
        float af[16];
#pragma unroll
        for (int m = 0; m < 4; m++) {
            af[m * 4 + 0] = cacc[m].x; af[m * 4 + 1] = cacc[m].y;
            af[m * 4 + 2] = cacc[m].z; af[m * 4 + 3] = cacc[m].w;
        }
        float e0 = b2s[0], e1 = b2s[1];
#pragma unroll
        for (int c2 = 0; c2 < 16; c2++) {
            float h = fmaxf(af[c2] + cb[c2], 0.f);
            e0 += h * w2s[c2][0];
            e1 += h * w2s[c2][1];
        }
        *(float2*)&g_em[(size_t)(p0 + tid) * 2] = make_float2(e0, e1);

        __threadfence();
        __syncthreads();
        if (tid == 0) atomicAdd(&g_cnt[p0 >> 11], 1u);
        return;
    }

    // =================== PHASE R: CRF (blocks 64..71) ===================
    const int b = bid - 64;
    const int wid = warp;
    const int len = tlen[b];
    const float t00 = trans[0], t01 = trans[1], t10 = trans[2], t11 = trans[3];
    const float* emb = g_em + (size_t)b * LL * 2;
    const float4 IDENT = make_float4(0.f, NEGINF, NEGINF, 0.f);

    // prefetch labels (independent of conv)
    const int* lab = labels + (size_t)b * LL;
    int labv[9];
#pragma unroll
    for (int k = 0; k < 9; k++) {
        int t = tid * 8 + k;
        labv[k] = (t < LL) ? lab[t] : 0;
    }
    // precompute exp of transitions (tiny)
    const float et00 = __expf(t00), et01 = __expf(t01);
    const float et10 = __expf(t10), et11 = __expf(t11);

    if (tid == 0) {
        while (*(volatile unsigned*)&g_cnt[b] < 8u) { }
    }
    __syncthreads();
    __threadfence();

    float2 em[8];
#pragma unroll
    for (int k = 0; k < 8; k++) {
        int t = tid * 8 + k + 1;
        em[k] = (t < LL) ? *(const float2*)(emb + 2 * t) : make_float2(0.f, 0.f);
    }

    // ---- forward chunk product in LINEAR space (scaled) ----
    float4 Lf = make_float4(1.f, 0.f, 0.f, 1.f);
    float Sf = 0.f;
    // ---- viterbi chunk product (max-plus, log space) ----
    float4 Pv;
    if (tid * 8 + 1 >= len) {
        Pv = IDENT;
    } else {
#pragma unroll
        for (int k = 0; k < 8; k++) {
            int t = tid * 8 + k + 1;
            if (t < len) {
                float m0 = em[k].x, m1 = em[k].y;
                float c = fmaxf(m0, m1);
                float p0 = __expf(m0 - c), p1 = __expf(m1 - c);
                float r0 = et00 * p0, r1 = et01 * p1;
                float r2 = et10 * p0, r3 = et11 * p1;
                float nx = Lf.x * r0 + Lf.y * r2;
                float ny = Lf.x * r1 + Lf.y * r3;
                float nz = Lf.z * r0 + Lf.w * r2;
                float nw = Lf.z * r1 + Lf.w * r3;
                Lf = make_float4(nx, ny, nz, nw);
                Sf += c;
            }
        }
        float4 M[8];
#pragma unroll
        for (int k = 0; k < 8; k++) {
            int t = tid * 8 + k + 1;
            M[k] = (t < len)
                ? make_float4(t00 + em[k].x, t01 + em[k].y, t10 + em[k].x, t11 + em[k].y)
                : IDENT;
        }
        float4 v01 = max_mm(M[0], M[1]), v23 = max_mm(M[2], M[3]);
        float4 v45 = max_mm(M[4], M[5]), v67 = max_mm(M[6], M[7]);
        Pv = max_mm(max_mm(v01, v23), max_mm(v45, v67));
    }

    // ---- forward: warp reduce in linear space (ordered, gated) ----
    {
        float4 r = Lf; float rs = Sf;
#pragma unroll
        for (int off = 1; off < 32; off <<= 1) {
            float4 o = shfl_dn4(r, off, FULL);
            float os = __shfl_down_sync(FULL, rs, off);
            if (lane + off < 32) lin_comb(r, rs, o, os);
        }
        if (lane == 0) { wf8[wid] = r; wfS[wid] = rs; }
    }

    // ---- viterbi: warp inclusive scan ----
    float4 s = Pv;
#pragma unroll
    for (int off = 1; off < 32; off <<= 1) {
        float4 o = shfl_up4(s, off, FULL);
        if (lane >= off) s = max_mm(o, s);
    }
    if (lane == 31) wv8[wid] = s;
    __syncthreads();

    if (wid == 0 && lane < 8) {
        float4 rf = wf8[lane]; float rfs = wfS[lane];
#pragma unroll
        for (int off = 1; off < 8; off <<= 1) {
            float4 o = shfl_dn4(rf, off, 0xffu);
            float os = __shfl_down_sync(0xffu, rfs, off);
            if (lane + off < 8) lin_comb(rf, rfs, o, os);
        }
        if (lane == 0) { pftot_s = rf; pftot_S = rfs; }

        float4 rv = wv8[lane];
#pragma unroll
        for (int off = 1; off < 8; off <<= 1) {
            float4 o = shfl_up4(rv, off, 0xffu);
            if (lane >= off) rv = max_mm(o, rv);
        }
        wvscan[lane] = rv;
    }
    __syncthreads();

    const float a00 = start_trans[0] + emb[0];
    const float a01 = start_trans[1] + emb[1];
    const float e0 = end_trans[0], e1 = end_trans[1];

    float4 PVt = wvscan[7];
    float v0 = fmaxf(a00 + PVt.x, a01 + PVt.z);
    float v1 = fmaxf(a00 + PVt.y, a01 + PVt.w);
    const int last = (v1 + e1 > v0 + e0) ? 1 : 0;

    float4 prev = shfl_up4(s, 1, FULL);
    float4 E;
    if (wid == 0) E = (lane == 0) ? IDENT : prev;
    else          E = (lane == 0) ? wvscan[wid - 1] : max_mm(wvscan[wid - 1], prev);

    float u0 = fmaxf(a00 + E.x, a01 + E.z);
    float u1 = fmaxf(a00 + E.y, a01 + E.w);
    unsigned g[8];
    unsigned cc = 2u;
#pragma unroll
    for (int k = 0; k < 8; k++) {
        int t = tid * 8 + k + 1;
        unsigned gt;
        if (t < len) {
            float m0 = em[k].x, m1 = em[k].y;
            float s00 = u0 + t00, s10 = u1 + t10;
            int i0 = (s10 > s00) ? 1 : 0;
            float n0 = fmaxf(s00, s10) + m0;
            float s01 = u0 + t01, s11 = u1 + t11;
            int i1 = (s11 > s01) ? 1 : 0;
            float n1 = fmaxf(s01, s11) + m1;
            gt = (unsigned)(i0 | (i1 << 1));
            u0 = n0; u1 = n1;
        } else {
            gt = 2u;
        }
        g[k] = gt;
        cc = comp2(cc, gt);
    }

    unsigned vsuf = cc;
#pragma unroll
    for (int off = 1; off < 32; off <<= 1) {
        unsigned o = __shfl_down_sync(FULL, vsuf, off);
        if (lane + off < 32) vsuf = comp2(vsuf, o);
    }
    if (lane == 0) wc[wid] = vsuf;
    __syncthreads();

    unsigned nv = __shfl_down_sync(FULL, vsuf, 1);
    unsigned within = (lane == 31) ? 2u : nv;
    unsigned ws = 2u;
#pragma unroll
    for (int j = 0; j < 8; j++)
        if (j > wid) ws = comp2(ws, wc[j]);
    unsigned suf_next = comp2(within, ws);
    unsigned xx = (suf_next >> last) & 1u;

    float* tout = out + 1 + (size_t)b * LL;
#pragma unroll
    for (int k = 7; k >= 0; k--) {
        xx = (g[k] >> xx) & 1u;
        int pos = tid * 8 + k;
        tout[pos] = (pos < len) ? (float)xx : 0.f;
    }

    float sc = 0.f;
#pragma unroll
    for (int k = 0; k < 8; k++) {
        int t = tid * 8 + k + 1;
        if (t < len) {
            int lp = labv[k], lc = labv[k + 1];
            sc += trans[lp * 2 + lc] + (lc ? em[k].y : em[k].x);
        }
    }
#pragma unroll
    for (int off = 1; off < 32; off <<= 1) {
        float o = __shfl_down_sync(FULL, sc, off);
        if (lane + off < 32) sc += o;
    }
    if (lane == 0) ss[wid] = sc;
    __syncthreads();

    if (tid == 0) {
        // norm from linear product + scale
        float4 PF = pftot_s;
        float PS = pftot_S;
        float ca = fmaxf(a00, a01);
        float va = __expf(a00 - ca), vb = __expf(a01 - ca);
        float r0 = va * PF.x + vb * PF.z;
        float r1 = va * PF.y + vb * PF.w;
        float q = r0 * __expf(e0) + r1 * __expf(e1);
        float norm = __logf(q) + PS + ca;

        float total = 0.f;
#pragma unroll
        for (int i = 0; i < 8; i++) total += ss[i];
        int l0 = lab[0];
        total += start_trans[l0] + emb[l0];
        int le = lab[len - 1];
        total += end_trans[le];
        g_llh[b] = total - norm;
        __threadfence();
        unsigned old = atomicAdd(&g_done, 1);
        if (old == BB - 1) {
            __threadfence();
            float sacc = 0.f;
#pragma unroll
            for (int i = 0; i < BB; i++) sacc += ((volatile float*)g_llh)[i];
            out[0] = -sacc;
            // reset all sync state for the next graph replay
            g_done = 0;
            g_prep = 0;
#pragma unroll
            for (int i = 0; i < BB; i++) g_cnt[i] = 0;
            for (int i = 0; i < 128; i++) g_stripe[i] = 0;
            __threadfence();
        }
    }
}

extern "C" void kernel_launch(void* const* d_in, const int* in_sizes, int n_in,
                              void* d_out, int out_size)
{
    const float* x       = (const float*)d_in[0];
    const int*   tlen    = (const int*)d_in[1];
    const int*   labels  = (const int*)d_in[2];
    const float* w1      = (const float*)d_in[3];
    const float* b1      = (const float*)d_in[4];
    const float* conv_w  = (const float*)d_in[5];
    const float* conv_b  = (const float*)d_in[6];
    const float* w2      = (const float*)d_in[7];
    const float* b2      = (const float*)d_in[8];
    const float* st      = (const float*)d_in[9];
    const float* en      = (const float*)d_in[10];
    const float* tr      = (const float*)d_in[11];
    float* out = (float*)d_out;

    fused_all<<<256, 256>>>(x, w1, b1, conv_w, conv_b, w2, b2,
                            tlen, labels, st, en, tr, out);
}